// round 16
// baseline (speedup 1.0000x reference)
#include <cuda_runtime.h>
#include <cuda_bf16.h>
#include <cstdint>
#include <math.h>

#define BB 2
#define SS 2048
#define HH 16
#define DD 128
#define HD 2048
#define WIN 256
#define GG 64
#define NPACK 2304   // 2048 q cols + 128 k_mean + 128 v_mean

// fragment-order operands
__device__ float g_apermH[(size_t)4096 * 2048];      // hidden, A_perm
__device__ float g_attnP[(size_t)4096 * 2048];       // attn out, A_perm
__device__ float g_wpackP[(size_t)18 * 64 * 4096];   // packed Wqkv, B_perm
__device__ float g_woP[(size_t)16 * 64 * 4096];      // Wo, B_perm
__device__ float g_bpack[NPACK];
__device__ float g_qraw[(size_t)BB * SS * NPACK];
__device__ float g_qf[(size_t)BB * 128 * 16 * 2048]; // q, attn A-fragment order
__device__ float g_km[(size_t)BB * SS * DD];         // tf32-rounded
__device__ float g_vm[(size_t)BB * SS * DD];         // tf32-rounded

__device__ __forceinline__ unsigned cvt_tf32_bits(float v) {
    unsigned t; asm("cvt.rna.tf32.f32 %0, %1;" : "=r"(t) : "f"(v)); return t;
}
__device__ __forceinline__ float cvt_tf32(float v) {
    return __uint_as_float(cvt_tf32_bits(v));
}
__device__ __forceinline__ void mma_tf32(float* acc, const unsigned* a, const unsigned* b) {
    asm volatile(
        "mma.sync.aligned.m16n8k8.row.col.f32.tf32.tf32.f32 "
        "{%0,%1,%2,%3}, {%4,%5,%6,%7}, {%8,%9}, {%0,%1,%2,%3};"
        : "+f"(acc[0]), "+f"(acc[1]), "+f"(acc[2]), "+f"(acc[3])
        : "r"(a[0]), "r"(a[1]), "r"(a[2]), "r"(a[3]), "r"(b[0]), "r"(b[1]));
}

// ---------------- A_perm builder: smem-tiled, coalesced both sides ----------------
__global__ __launch_bounds__(256)
void a_perm(const float* __restrict__ X, float* __restrict__ out)
{
    __shared__ float t[128][33];
    int brow = blockIdx.x >> 6, kt = blockIdx.x & 63;
    const float* src = X + (size_t)brow * 128 * 2048 + kt * 32;
    int r0 = threadIdx.x >> 1, c0 = (threadIdx.x & 1) * 16;
#pragma unroll
    for (int j = 0; j < 16; j += 4) {
        float4 v = *(const float4*)(src + (size_t)r0 * 2048 + c0 + j);
        t[r0][c0 + j] = v.x; t[r0][c0 + j + 1] = v.y;
        t[r0][c0 + j + 2] = v.z; t[r0][c0 + j + 3] = v.w;
    }
    __syncthreads();
    float* dst = out + ((size_t)(brow * 64 + kt)) * 4096;
    for (int idx = threadIdx.x; idx < 4096; idx += 256) {
        int r = idx & 3, lane = (idx >> 2) & 31, mt = (idx >> 7) & 7, ks = (idx >> 10) & 3;
        int m = mt * 16 + (lane >> 2) + (r & 1) * 8;
        int k = ks * 8 + (lane & 3) + (r >> 1) * 4;
        dst[idx] = cvt_tf32(t[m][k]);
    }
}

// ---------------- B_perm builder ----------------
__global__ __launch_bounds__(256)
void pack_w_perm(const float* __restrict__ W, float* __restrict__ out,
                 int nbcol, int mode)
{
    long i = (long)blockIdx.x * 256 + threadIdx.x;
    if (i >= (long)nbcol * 262144) return;
    int j = i & 1, lane = (i >> 1) & 31, nt = (i >> 6) & 15;
    int ks = (i >> 10) & 3, kt = (i >> 12) & 63, bcol = (int)(i >> 18);
    int np = bcol * 128 + nt * 8 + (lane >> 2);
    int kk = kt * 32 + ks * 8 + (lane & 3) + j * 4;
    float v;
    if (mode == 0) {
        v = W[(size_t)kk * 2048 + np];
    } else if (np < 2048) {
        v = W[(size_t)kk * 6144 + (np >> 7) * 384 + (np & 127)];
    } else {
        int off = 128 + (np - 2048);
        float s = 0.f;
#pragma unroll
        for (int h = 0; h < 16; ++h) s += W[(size_t)kk * 6144 + h * 384 + off];
        v = s * 0.0625f;
    }
    out[i] = cvt_tf32(v);
}

__global__ __launch_bounds__(256)
void pack_b(const float* __restrict__ bq, float* __restrict__ bp)
{
    int n = blockIdx.x * 256 + threadIdx.x;
    if (n >= NPACK) return;
    float v;
    if (n < 2048) v = bq[(n >> 7) * 384 + (n & 127)];
    else {
        int off = 128 + (n - 2048);
        float s = 0.f;
#pragma unroll
        for (int h = 0; h < 16; ++h) s += bq[h * 384 + off];
        v = s * 0.0625f;
    }
    bp[n] = v;
}

// ---------------- TF32 GEMM, fragment-order operands; prefetch BEFORE compute ----------------
#define STG_FLOATS 8192
#define NSTAGE 3
#define GEMM_SMEM_BYTES (NSTAGE * STG_FLOATS * 4)

__global__ __launch_bounds__(256, 2)
void tf32_gemm_perm(const float* __restrict__ Ap, const float* __restrict__ Bp,
                    const float* __restrict__ bias, float* __restrict__ C,
                    int M, int N, int K)
{
    extern __shared__ float smem_g[];
    const int tid = threadIdx.x, lane = tid & 31, warp = tid >> 5;
    const int wm = warp >> 2, wn = warp & 3;
    const int brow = blockIdx.y, bcol = blockIdx.x;
    const int nk = K >> 5;
    const float* Abase = Ap + (size_t)brow * nk * 4096;
    const float* Bbase = Bp + (size_t)bcol * nk * 4096;

    float acc[4][4][4];
#pragma unroll
    for (int i = 0; i < 4; i++)
#pragma unroll
        for (int j = 0; j < 4; j++)
#pragma unroll
            for (int r = 0; r < 4; r++) acc[i][j][r] = 0.f;

    auto issue = [&](int kt) {
        float* st = smem_g + (kt % NSTAGE) * STG_FLOATS;
        const float* sa = Abase + (size_t)kt * 4096;
        const float* sb = Bbase + (size_t)kt * 4096;
#pragma unroll
        for (int l = 0; l < 4; ++l) {
            int ca = l * 256 + tid;
            unsigned da = (unsigned)__cvta_generic_to_shared(st + ca * 4);
            asm volatile("cp.async.cg.shared.global [%0], [%1], 16;\n"
                         :: "r"(da), "l"(sa + ca * 4));
            unsigned db = (unsigned)__cvta_generic_to_shared(st + 4096 + ca * 4);
            asm volatile("cp.async.cg.shared.global [%0], [%1], 16;\n"
                         :: "r"(db), "l"(sb + ca * 4));
        }
    };

    auto compute = [&](int s) {
        const float* Ast = smem_g + s * STG_FLOATS;
        const float* Bst = Ast + 4096;
#pragma unroll
        for (int ks = 0; ks < 4; ++ks) {
            unsigned af[4][4], bf[4][2];
#pragma unroll
            for (int mil = 0; mil < 4; ++mil) {
                float4 v = *(const float4*)(Ast + ((ks * 8 + wm * 4 + mil) * 32 + lane) * 4);
                af[mil][0] = __float_as_uint(v.x);
                af[mil][1] = __float_as_uint(v.y);
                af[mil][2] = __float_as_uint(v.z);
                af[mil][3] = __float_as_uint(v.w);
            }
#pragma unroll
            for (int nil = 0; nil < 4; ++nil) {
                float2 v = *(const float2*)(Bst + ((ks * 16 + wn * 4 + nil) * 32 + lane) * 2);
                bf[nil][0] = __float_as_uint(v.x);
                bf[nil][1] = __float_as_uint(v.y);
            }
#pragma unroll
            for (int mil = 0; mil < 4; ++mil)
#pragma unroll
                for (int nil = 0; nil < 4; ++nil)
                    mma_tf32(acc[mil][nil], af[mil], bf[nil]);
        }
    };

    issue(0); asm volatile("cp.async.commit_group;");
    issue(1); asm volatile("cp.async.commit_group;");
    for (int kt = 0; kt < nk; ++kt) {
        asm volatile("cp.async.wait_group 1;");   // stage kt resident
        __syncthreads();                          // everyone done with stage kt-1
        if (kt + 2 < nk) issue(kt + 2);           // prefetch BEFORE compute
        asm volatile("cp.async.commit_group;");
        compute(kt % NSTAGE);
    }

    const int g = lane >> 2, tig = lane & 3;
#pragma unroll
    for (int mil = 0; mil < 4; ++mil)
#pragma unroll
        for (int nil = 0; nil < 4; ++nil) {
            int row0 = brow * 128 + wm * 64 + mil * 16 + g;
            int col  = bcol * 128 + wn * 32 + nil * 8 + tig * 2;
            float b0 = bias[col], b1 = bias[col + 1];
            *(float2*)(C + (size_t)row0 * N + col) =
                make_float2(acc[mil][nil][0] + b0, acc[mil][nil][1] + b1);
            *(float2*)(C + (size_t)(row0 + 8) * N + col) =
                make_float2(acc[mil][nil][2] + b0, acc[mil][nil][3] + b1);
        }
}

// ---------------- RoPE + split; q fragment-order; km/vm tf32-rounded ----------------
__global__ __launch_bounds__(128)
void rope_split_kernel(const float* __restrict__ qraw, float* __restrict__ qf,
                       float* __restrict__ km, float* __restrict__ vm)
{
    int bs = blockIdx.x;
    int b = bs >> 11, s = bs & 2047;
    int d = threadIdx.x;
    const float* bp = qraw + (size_t)bs * NPACK;
    const float scale = 0.08838834764831845f;

    float c = 1.f, sn = 0.f;
    float sgn = (d < 16) ? -1.f : 1.f;
    if (d < 32) {
        float invf = (float)exp2(-(double)(d & 15) / 16.0 * log2(10000.0));
        float ang = (float)s * invf;
        c = (float)cos((double)ang);
        sn = (float)sin((double)ang);
    }

    float kv = bp[2048 + d];
    float vv = bp[2176 + d];
    float kp = __shfl_xor_sync(0xffffffffu, kv, 16);
    if (d < 32) kv = kv * c + sgn * kp * sn;
    km[(size_t)bs * 128 + d] = cvt_tf32(kv);
    vm[(size_t)bs * 128 + d] = cvt_tf32(vv);

    int qt = s >> 4, qi = s & 15;
    int lane = (qi & 7) * 4 + (d & 3);
    int r = (qi >> 3) + ((d >> 2) & 1) * 2;
    int ks = d >> 3;
    float* base = qf + ((size_t)(b * 128 + qt) * 16) * 2048 + ks * 128 + lane * 4 + r;
#pragma unroll
    for (int h = 0; h < 16; ++h) {
        float qv = bp[h * 128 + d];
        float qp = __shfl_xor_sync(0xffffffffu, qv, 16);
        float qr = (d < 32) ? (qv * c + sgn * qp * sn) : qv;
        base[(size_t)h * 2048] = cvt_tf32(qr * scale);
    }
}

// ---------------- MMA attention: db K/V, index-based window masking ----------------
#define KSTG 8448
#define VSTG 8704
#define OFF_K0   0
#define OFF_V0   16896
#define OFF_P    34304
#define OFF_KPOS 51712
#define OFF_KADD 52096
#define ATTN2_FLOATS 52480
#define ATTN2_BYTES (ATTN2_FLOATS * 4)

__global__ __launch_bounds__(512, 1)
void attn_mma(const float* __restrict__ qf, const float* __restrict__ km,
              const float* __restrict__ vm, const float* __restrict__ mask,
              const int* __restrict__ gidx, float* __restrict__ attnP)
{
    extern __shared__ float sm[];
    int* kpos = (int*)(sm + OFF_KPOS);
    float* kadd = sm + OFF_KADD;

    const int qt = blockIdx.x, qp0 = qt * 16, b = blockIdx.y;
    const int tid = threadIdx.x, warp = tid >> 5, lane = tid & 31;
    const int g = lane >> 2, tig = lane & 3;
    const bool caseA = (qp0 >= WIN);
    const int NCH = caseA ? 6 : ((qp0 + 79) >> 6);

    for (int j = tid; j < 384; j += 512) {
        int pos = 1 << 27; float ka = 0.f;
        if (caseA) {
            if (j < 64) pos = gidx[b * GG + j];
            else { int p = qp0 - 255 + (j - 64);
                   if (p < SS) { pos = p; ka = mask[b * SS + p]; } }
        } else if (j < qp0 + 16) { pos = j; ka = mask[b * SS + j]; }
        kpos[j] = pos; kadd[j] = ka;
    }
    __syncthreads();

    auto issue = [&](int ch) {
        int cb = ch << 6;
        int r = tid >> 3, q8 = (tid & 7) * 16;
        int pos = kpos[cb + r]; if (pos >= SS) pos = 0;
        const float* kvp = km + ((size_t)b * SS + pos) * 128 + q8;
        const float* vvp = vm + ((size_t)b * SS + pos) * 128 + q8;
        unsigned kd = (unsigned)__cvta_generic_to_shared(
            sm + OFF_K0 + (ch & 1) * KSTG + r * 132 + q8);
        unsigned vd = (unsigned)__cvta_generic_to_shared(
            sm + OFF_V0 + (ch & 1) * VSTG + r * 136 + q8);
#pragma unroll
        for (int j = 0; j < 4; ++j) {
            asm volatile("cp.async.cg.shared.global [%0], [%1], 16;\n"
                         :: "r"(kd + j * 16), "l"(kvp + j * 4));
            asm volatile("cp.async.cg.shared.global [%0], [%1], 16;\n"
                         :: "r"(vd + j * 16), "l"(vvp + j * 4));
        }
    };

    const int h = warp;
    const float* qfb = qf + ((size_t)(b * 128 + qt) * 16 + h) * 2048;

    float m0 = -1e30f, m1 = -1e30f, l0 = 0.f, l1 = 0.f;
    float oacc[16][4];
#pragma unroll
    for (int dt = 0; dt < 16; ++dt)
#pragma unroll
        for (int e = 0; e < 4; ++e) oacc[dt][e] = 0.f;

    float* Pw = sm + OFF_P + warp * 1088;

    issue(0);
    asm volatile("cp.async.commit_group;");

    for (int ch = 0; ch < NCH; ++ch) {
        if (ch + 1 < NCH) issue(ch + 1);
        asm volatile("cp.async.commit_group;");
        asm volatile("cp.async.wait_group 1;");
        __syncthreads();

        const int cb = ch << 6;
        const bool isglob = caseA && (ch == 0);
        const float* Kst = sm + OFF_K0 + (ch & 1) * KSTG;
        const float* Vst = sm + OFF_V0 + (ch & 1) * VSTG;

        float S[8][4];
#pragma unroll
        for (int nt = 0; nt < 8; ++nt)
#pragma unroll
            for (int e = 0; e < 4; ++e) S[nt][e] = 0.f;
#pragma unroll
        for (int ks = 0; ks < 16; ++ks) {
            float4 qv = *(const float4*)(qfb + ks * 128 + lane * 4);
            unsigned af[4] = {__float_as_uint(qv.x), __float_as_uint(qv.y),
                              __float_as_uint(qv.z), __float_as_uint(qv.w)};
#pragma unroll
            for (int nt = 0; nt < 8; ++nt) {
                const float* pk = Kst + (nt * 8 + g) * 132 + ks * 8 + tig;
                unsigned bf[2] = {__float_as_uint(pk[0]), __float_as_uint(pk[4])};
                mma_tf32(S[nt], af, bf);
            }
        }

        // mask: window/causal validity via index arithmetic; kpos only for globals
        float mc0 = -2e30f, mc1 = -2e30f;
#pragma unroll
        for (int nt = 0; nt < 8; ++nt) {
            int s0 = cb + nt * 8 + 2 * tig;
#pragma unroll
            for (int e = 0; e < 2; ++e) {
                int j = s0 + e;
                float ka = kadd[j];
                bool v0, v1;
                if (isglob) {
                    int p = kpos[j];
                    v0 = p < qp0 + g - 256;
                    v1 = p < qp0 + g - 248;
                } else if (caseA) {
                    int jw = j - 64;
                    v0 = (unsigned)(jw - g) <= 255u;
                    v1 = (unsigned)(jw - g - 8) <= 255u;
                } else {
                    v0 = j <= qp0 + g;
                    v1 = j <= qp0 + g + 8;
                }
                S[nt][e]     = v0 ? S[nt][e] + ka     : -2e30f;
                S[nt][e + 2] = v1 ? S[nt][e + 2] + ka : -2e30f;
                mc0 = fmaxf(mc0, S[nt][e]);
                mc1 = fmaxf(mc1, S[nt][e + 2]);
            }
        }
        mc0 = fmaxf(mc0, __shfl_xor_sync(~0u, mc0, 1));
        mc0 = fmaxf(mc0, __shfl_xor_sync(~0u, mc0, 2));
        mc1 = fmaxf(mc1, __shfl_xor_sync(~0u, mc1, 1));
        mc1 = fmaxf(mc1, __shfl_xor_sync(~0u, mc1, 2));
        float mn0 = fmaxf(m0, mc0), mn1 = fmaxf(m1, mc1);
        float cr0 = __expf(m0 - mn0), cr1 = __expf(m1 - mn1);
        m0 = mn0; m1 = mn1;
        float lc0 = 0.f, lc1 = 0.f;
#pragma unroll
        for (int nt = 0; nt < 8; ++nt) {
            S[nt][0] = __expf(S[nt][0] - mn0); S[nt][1] = __expf(S[nt][1] - mn0);
            S[nt][2] = __expf(S[nt][2] - mn1); S[nt][3] = __expf(S[nt][3] - mn1);
            lc0 += S[nt][0] + S[nt][1]; lc1 += S[nt][2] + S[nt][3];
        }
        lc0 += __shfl_xor_sync(~0u, lc0, 1); lc0 += __shfl_xor_sync(~0u, lc0, 2);
        lc1 += __shfl_xor_sync(~0u, lc1, 1); lc1 += __shfl_xor_sync(~0u, lc1, 2);
        l0 = l0 * cr0 + lc0; l1 = l1 * cr1 + lc1;
#pragma unroll
        for (int dt = 0; dt < 16; ++dt) {
            oacc[dt][0] *= cr0; oacc[dt][1] *= cr0;
            oacc[dt][2] *= cr1; oacc[dt][3] *= cr1;
        }
#pragma unroll
        for (int nt = 0; nt < 8; ++nt) {
            int col = nt * 8 + 2 * tig;
            *(float2*)(Pw + g * 68 + col) =
                make_float2(cvt_tf32(S[nt][0]), cvt_tf32(S[nt][1]));
            *(float2*)(Pw + (g + 8) * 68 + col) =
                make_float2(cvt_tf32(S[nt][2]), cvt_tf32(S[nt][3]));
        }
        __syncwarp();

#pragma unroll
        for (int pk = 0; pk < 8; ++pk) {
            const float* ph = Pw + pk * 8 + tig;
            unsigned ah[4] = {__float_as_uint(ph[g * 68]),
                              __float_as_uint(ph[(g + 8) * 68]),
                              __float_as_uint(ph[g * 68 + 4]),
                              __float_as_uint(ph[(g + 8) * 68 + 4])};
#pragma unroll
            for (int dt = 0; dt < 16; ++dt) {
                const float* vh = Vst + (pk * 8 + tig) * 136 + dt * 8 + g;
                unsigned bh[2] = {__float_as_uint(vh[0]), __float_as_uint(vh[4 * 136])};
                mma_tf32(oacc[dt], ah, bh);
            }
        }
        __syncthreads();
    }

    // epilogue: write A_perm fragment-order global for GEMM2
    const float inv0 = 1.f / l0, inv1 = 1.f / l1;
    const int browA = (b * SS + qp0) >> 7;
    const int mt = (qp0 >> 4) & 7;
#pragma unroll
    for (int dt = 0; dt < 16; ++dt) {
#pragma unroll
        for (int e = 0; e < 4; ++e) {
            int k = h * 128 + dt * 8 + tig * 2 + (e & 1);
            int kt = k >> 5, ks = (k >> 3) & 3;
            int lanep = g * 4 + (k & 3);
            int r = ((e >> 1) & 1) + ((k >> 2) & 1) * 2;
            size_t off = ((size_t)(browA * 64 + kt)) * 4096
                       + (size_t)((ks * 8 + mt) * 128 + lanep * 4 + r);
            float sc = (e < 2) ? inv0 : inv1;
            attnP[off] = cvt_tf32(oacc[dt][e] * sc);
        }
    }
}

// ---------------------------------------------------------------------------
extern "C" void kernel_launch(void* const* d_in, const int* in_sizes, int n_in,
                              void* d_out, int out_size)
{
    const float* hidden = (const float*)d_in[0];
    const float* mask   = (const float*)d_in[1];
    const int*   gidx   = (const int*)d_in[2];
    const float* Wqkv   = (const float*)d_in[3];
    const float* bqkv   = (const float*)d_in[4];
    const float* Wo     = (const float*)d_in[5];
    const float* bo     = (const float*)d_in[6];
    float* out = (float*)d_out;

    float *apermH, *attnP, *wpackP, *woP, *bpack, *qraw, *qfb, *kmp, *vmp;
    cudaGetSymbolAddress((void**)&apermH, g_apermH);
    cudaGetSymbolAddress((void**)&attnP,  g_attnP);
    cudaGetSymbolAddress((void**)&wpackP, g_wpackP);
    cudaGetSymbolAddress((void**)&woP,    g_woP);
    cudaGetSymbolAddress((void**)&bpack,  g_bpack);
    cudaGetSymbolAddress((void**)&qraw,   g_qraw);
    cudaGetSymbolAddress((void**)&qfb,    g_qf);
    cudaGetSymbolAddress((void**)&kmp,    g_km);
    cudaGetSymbolAddress((void**)&vmp,    g_vm);

    cudaFuncSetAttribute(attn_mma, cudaFuncAttributeMaxDynamicSharedMemorySize,
                         ATTN2_BYTES);
    cudaFuncSetAttribute(tf32_gemm_perm, cudaFuncAttributeMaxDynamicSharedMemorySize,
                         GEMM_SMEM_BYTES);

    // 0) operand prep (all fragment-order)
    pack_w_perm<<<(unsigned)(((long)18 * 262144 + 255) / 256), 256>>>(Wqkv, wpackP, 18, 1);
    pack_w_perm<<<(unsigned)(((long)16 * 262144 + 255) / 256), 256>>>(Wo, woP, 16, 0);
    pack_b<<<(NPACK + 255) / 256, 256>>>(bqkv, bpack);
    a_perm<<<2048, 256>>>(hidden, apermH);

    // 1) fused Q + head-mean-KV GEMM
    tf32_gemm_perm<<<dim3(NPACK / 128, 4096 / 128), 256, GEMM_SMEM_BYTES>>>(
        apermH, wpackP, bpack, qraw, 4096, NPACK, 2048);

    // 2) RoPE + split; q -> fragment order, km/vm tf32-rounded
    rope_split_kernel<<<BB * SS, 128>>>(qraw, qfb, kmp, vmp);

    // 3) MMA attention (async double-buffered K/V; writes GEMM2 A_perm)
    attn_mma<<<dim3(SS / 16, BB), 512, ATTN2_BYTES>>>(
        qfb, kmp, vmp, mask, gidx, attnP);

    // 4) Output GEMM
    tf32_gemm_perm<<<dim3(2048 / 128, 4096 / 128), 256, GEMM_SMEM_BYTES>>>(
        attnP, woP, bo, out, 4096, 2048, 2048);
}

// round 17
// speedup vs baseline: 1.0736x; 1.0736x over previous
#include <cuda_runtime.h>
#include <cuda_bf16.h>
#include <cstdint>
#include <math.h>

#define BB 2
#define SS 2048
#define HH 16
#define DD 128
#define HD 2048
#define WIN 256
#define GG 64
#define NPACK 2304   // 2048 q cols + 128 k_mean + 128 v_mean

// fragment-order operands
__device__ float g_apermH[(size_t)4096 * 2048];      // hidden, A_perm
__device__ float g_attnP[(size_t)4096 * 2048];       // attn out, A_perm
__device__ float g_wpackP[(size_t)18 * 64 * 4096];   // packed Wqkv, B_perm
__device__ float g_woP[(size_t)16 * 64 * 4096];      // Wo, B_perm
__device__ float g_bpack[NPACK];
__device__ float g_qraw[(size_t)BB * SS * NPACK];
__device__ float g_qf[(size_t)BB * 128 * 16 * 2048]; // q, attn A-fragment order
__device__ float g_km[(size_t)BB * SS * DD];         // tf32-rounded
__device__ float g_vm[(size_t)BB * SS * DD];         // tf32-rounded

__device__ __forceinline__ unsigned cvt_tf32_bits(float v) {
    unsigned t; asm("cvt.rna.tf32.f32 %0, %1;" : "=r"(t) : "f"(v)); return t;
}
__device__ __forceinline__ float cvt_tf32(float v) {
    return __uint_as_float(cvt_tf32_bits(v));
}
__device__ __forceinline__ void mma_tf32(float* acc, const unsigned* a, const unsigned* b) {
    asm volatile(
        "mma.sync.aligned.m16n8k8.row.col.f32.tf32.tf32.f32 "
        "{%0,%1,%2,%3}, {%4,%5,%6,%7}, {%8,%9}, {%0,%1,%2,%3};"
        : "+f"(acc[0]), "+f"(acc[1]), "+f"(acc[2]), "+f"(acc[3])
        : "r"(a[0]), "r"(a[1]), "r"(a[2]), "r"(a[3]), "r"(b[0]), "r"(b[1]));
}

// ---------------- A_perm builder: smem-tiled, coalesced both sides (R16 win) ----------------
__global__ __launch_bounds__(256)
void a_perm(const float* __restrict__ X, float* __restrict__ out)
{
    __shared__ float t[128][33];
    int brow = blockIdx.x >> 6, kt = blockIdx.x & 63;
    const float* src = X + (size_t)brow * 128 * 2048 + kt * 32;
    int r0 = threadIdx.x >> 1, c0 = (threadIdx.x & 1) * 16;
#pragma unroll
    for (int j = 0; j < 16; j += 4) {
        float4 v = *(const float4*)(src + (size_t)r0 * 2048 + c0 + j);
        t[r0][c0 + j] = v.x; t[r0][c0 + j + 1] = v.y;
        t[r0][c0 + j + 2] = v.z; t[r0][c0 + j + 3] = v.w;
    }
    __syncthreads();
    float* dst = out + ((size_t)(brow * 64 + kt)) * 4096;
    for (int idx = threadIdx.x; idx < 4096; idx += 256) {
        int r = idx & 3, lane = (idx >> 2) & 31, mt = (idx >> 7) & 7, ks = (idx >> 10) & 3;
        int m = mt * 16 + (lane >> 2) + (r & 1) * 8;
        int k = ks * 8 + (lane & 3) + (r >> 1) * 4;
        dst[idx] = cvt_tf32(t[m][k]);
    }
}

// ---------------- B_perm builder ----------------
__global__ __launch_bounds__(256)
void pack_w_perm(const float* __restrict__ W, float* __restrict__ out,
                 int nbcol, int mode)
{
    long i = (long)blockIdx.x * 256 + threadIdx.x;
    if (i >= (long)nbcol * 262144) return;
    int j = i & 1, lane = (i >> 1) & 31, nt = (i >> 6) & 15;
    int ks = (i >> 10) & 3, kt = (i >> 12) & 63, bcol = (int)(i >> 18);
    int np = bcol * 128 + nt * 8 + (lane >> 2);
    int kk = kt * 32 + ks * 8 + (lane & 3) + j * 4;
    float v;
    if (mode == 0) {
        v = W[(size_t)kk * 2048 + np];
    } else if (np < 2048) {
        v = W[(size_t)kk * 6144 + (np >> 7) * 384 + (np & 127)];
    } else {
        int off = 128 + (np - 2048);
        float s = 0.f;
#pragma unroll
        for (int h = 0; h < 16; ++h) s += W[(size_t)kk * 6144 + h * 384 + off];
        v = s * 0.0625f;
    }
    out[i] = cvt_tf32(v);
}

__global__ __launch_bounds__(256)
void pack_b(const float* __restrict__ bq, float* __restrict__ bp)
{
    int n = blockIdx.x * 256 + threadIdx.x;
    if (n >= NPACK) return;
    float v;
    if (n < 2048) v = bq[(n >> 7) * 384 + (n & 127)];
    else {
        int off = 128 + (n - 2048);
        float s = 0.f;
#pragma unroll
        for (int h = 0; h < 16; ++h) s += bq[h * 384 + off];
        v = s * 0.0625f;
    }
    bp[n] = v;
}

// ---------------- TF32 GEMM on fragment-order operands (R15 ordering, proven) ----------------
#define STG_FLOATS 8192
#define NSTAGE 3
#define GEMM_SMEM_BYTES (NSTAGE * STG_FLOATS * 4)

__global__ __launch_bounds__(256, 2)
void tf32_gemm_perm(const float* __restrict__ Ap, const float* __restrict__ Bp,
                    const float* __restrict__ bias, float* __restrict__ C,
                    int M, int N, int K)
{
    extern __shared__ float smem_g[];
    const int tid = threadIdx.x, lane = tid & 31, warp = tid >> 5;
    const int wm = warp >> 2, wn = warp & 3;
    const int brow = blockIdx.y, bcol = blockIdx.x;
    const int nk = K >> 5;
    const float* Abase = Ap + (size_t)brow * nk * 4096;
    const float* Bbase = Bp + (size_t)bcol * nk * 4096;

    float acc[4][4][4];
#pragma unroll
    for (int i = 0; i < 4; i++)
#pragma unroll
        for (int j = 0; j < 4; j++)
#pragma unroll
            for (int r = 0; r < 4; r++) acc[i][j][r] = 0.f;

    auto issue = [&](int kt) {
        float* st = smem_g + (kt % NSTAGE) * STG_FLOATS;
        const float* sa = Abase + (size_t)kt * 4096;
        const float* sb = Bbase + (size_t)kt * 4096;
#pragma unroll
        for (int l = 0; l < 4; ++l) {
            int ca = l * 256 + tid;
            unsigned da = (unsigned)__cvta_generic_to_shared(st + ca * 4);
            asm volatile("cp.async.cg.shared.global [%0], [%1], 16;\n"
                         :: "r"(da), "l"(sa + ca * 4));
            unsigned db = (unsigned)__cvta_generic_to_shared(st + 4096 + ca * 4);
            asm volatile("cp.async.cg.shared.global [%0], [%1], 16;\n"
                         :: "r"(db), "l"(sb + ca * 4));
        }
    };

    auto compute = [&](int s) {
        const float* Ast = smem_g + s * STG_FLOATS;
        const float* Bst = Ast + 4096;
#pragma unroll
        for (int ks = 0; ks < 4; ++ks) {
            unsigned af[4][4], bf[4][2];
#pragma unroll
            for (int mil = 0; mil < 4; ++mil) {
                float4 v = *(const float4*)(Ast + ((ks * 8 + wm * 4 + mil) * 32 + lane) * 4);
                af[mil][0] = __float_as_uint(v.x);
                af[mil][1] = __float_as_uint(v.y);
                af[mil][2] = __float_as_uint(v.z);
                af[mil][3] = __float_as_uint(v.w);
            }
#pragma unroll
            for (int nil = 0; nil < 4; ++nil) {
                float2 v = *(const float2*)(Bst + ((ks * 16 + wn * 4 + nil) * 32 + lane) * 2);
                bf[nil][0] = __float_as_uint(v.x);
                bf[nil][1] = __float_as_uint(v.y);
            }
#pragma unroll
            for (int mil = 0; mil < 4; ++mil)
#pragma unroll
                for (int nil = 0; nil < 4; ++nil)
                    mma_tf32(acc[mil][nil], af[mil], bf[nil]);
        }
    };

    issue(0); asm volatile("cp.async.commit_group;");
    issue(1); asm volatile("cp.async.commit_group;");
    for (int kt = 0; kt < nk; ++kt) {
        asm volatile("cp.async.wait_group 1;");
        __syncthreads();
        compute(kt % NSTAGE);
        if (kt + 2 < nk) issue(kt + 2);
        asm volatile("cp.async.commit_group;");
    }

    const int g = lane >> 2, tig = lane & 3;
#pragma unroll
    for (int mil = 0; mil < 4; ++mil)
#pragma unroll
        for (int nil = 0; nil < 4; ++nil) {
            int row0 = brow * 128 + wm * 64 + mil * 16 + g;
            int col  = bcol * 128 + wn * 32 + nil * 8 + tig * 2;
            float b0 = bias[col], b1 = bias[col + 1];
            *(float2*)(C + (size_t)row0 * N + col) =
                make_float2(acc[mil][nil][0] + b0, acc[mil][nil][1] + b1);
            *(float2*)(C + (size_t)(row0 + 8) * N + col) =
                make_float2(acc[mil][nil][2] + b0, acc[mil][nil][3] + b1);
        }
}

// ---------------- RoPE + split; q fragment-order; km/vm tf32-rounded ----------------
__global__ __launch_bounds__(128)
void rope_split_kernel(const float* __restrict__ qraw, float* __restrict__ qf,
                       float* __restrict__ km, float* __restrict__ vm)
{
    int bs = blockIdx.x;
    int b = bs >> 11, s = bs & 2047;
    int d = threadIdx.x;
    const float* bp = qraw + (size_t)bs * NPACK;
    const float scale = 0.08838834764831845f;

    float c = 1.f, sn = 0.f;
    float sgn = (d < 16) ? -1.f : 1.f;
    if (d < 32) {
        float invf = (float)exp2(-(double)(d & 15) / 16.0 * log2(10000.0));
        float ang = (float)s * invf;
        c = (float)cos((double)ang);
        sn = (float)sin((double)ang);
    }

    float kv = bp[2048 + d];
    float vv = bp[2176 + d];
    float kp = __shfl_xor_sync(0xffffffffu, kv, 16);
    if (d < 32) kv = kv * c + sgn * kp * sn;
    km[(size_t)bs * 128 + d] = cvt_tf32(kv);
    vm[(size_t)bs * 128 + d] = cvt_tf32(vv);

    int qt = s >> 4, qi = s & 15;
    int lane = (qi & 7) * 4 + (d & 3);
    int r = (qi >> 3) + ((d >> 2) & 1) * 2;
    int ks = d >> 3;
    float* base = qf + ((size_t)(b * 128 + qt) * 16) * 2048 + ks * 128 + lane * 4 + r;
#pragma unroll
    for (int h = 0; h < 16; ++h) {
        float qv = bp[h * 128 + d];
        float qp = __shfl_xor_sync(0xffffffffu, qv, 16);
        float qr = (d < 32) ? (qv * c + sgn * qp * sn) : qv;
        base[(size_t)h * 2048] = cvt_tf32(qr * scale);
    }
}

// ---------------- MMA attention (R15 proven: db K/V, kpos-based masking) ----------------
#define KSTG 8448
#define VSTG 8704
#define OFF_K0   0
#define OFF_V0   16896
#define OFF_P    34304
#define OFF_KPOS 51712
#define OFF_KADD 52096
#define ATTN2_FLOATS 52480
#define ATTN2_BYTES (ATTN2_FLOATS * 4)

__global__ __launch_bounds__(512, 1)
void attn_mma(const float* __restrict__ qf, const float* __restrict__ km,
              const float* __restrict__ vm, const float* __restrict__ mask,
              const int* __restrict__ gidx, float* __restrict__ attnP)
{
    extern __shared__ float sm[];
    int* kpos = (int*)(sm + OFF_KPOS);
    float* kadd = sm + OFF_KADD;

    const int qt = blockIdx.x, qp0 = qt * 16, b = blockIdx.y;
    const int tid = threadIdx.x, warp = tid >> 5, lane = tid & 31;
    const int g = lane >> 2, tig = lane & 3;
    const bool caseA = (qp0 >= WIN);
    const int NCH = caseA ? 6 : ((qp0 + 79) >> 6);

    for (int j = tid; j < 384; j += 512) {
        int pos = 1 << 27; float ka = 0.f;
        if (caseA) {
            if (j < 64) pos = gidx[b * GG + j];
            else { int p = qp0 - 255 + (j - 64);
                   if (p < SS) { pos = p; ka = mask[b * SS + p]; } }
        } else if (j < qp0 + 16) { pos = j; ka = mask[b * SS + j]; }
        kpos[j] = pos; kadd[j] = ka;
    }
    __syncthreads();

    auto issue = [&](int ch) {
        int cb = ch << 6;
        int r = tid >> 3, q8 = (tid & 7) * 16;
        int pos = kpos[cb + r]; if (pos >= SS) pos = 0;
        const float* kvp = km + ((size_t)b * SS + pos) * 128 + q8;
        const float* vvp = vm + ((size_t)b * SS + pos) * 128 + q8;
        unsigned kd = (unsigned)__cvta_generic_to_shared(
            sm + OFF_K0 + (ch & 1) * KSTG + r * 132 + q8);
        unsigned vd = (unsigned)__cvta_generic_to_shared(
            sm + OFF_V0 + (ch & 1) * VSTG + r * 136 + q8);
#pragma unroll
        for (int j = 0; j < 4; ++j) {
            asm volatile("cp.async.cg.shared.global [%0], [%1], 16;\n"
                         :: "r"(kd + j * 16), "l"(kvp + j * 4));
            asm volatile("cp.async.cg.shared.global [%0], [%1], 16;\n"
                         :: "r"(vd + j * 16), "l"(vvp + j * 4));
        }
    };

    const int h = warp;
    const float* qfb = qf + ((size_t)(b * 128 + qt) * 16 + h) * 2048;

    float m0 = -1e30f, m1 = -1e30f, l0 = 0.f, l1 = 0.f;
    float oacc[16][4];
#pragma unroll
    for (int dt = 0; dt < 16; ++dt)
#pragma unroll
        for (int e = 0; e < 4; ++e) oacc[dt][e] = 0.f;

    float* Pw = sm + OFF_P + warp * 1088;

    issue(0);
    asm volatile("cp.async.commit_group;");

    for (int ch = 0; ch < NCH; ++ch) {
        if (ch + 1 < NCH) issue(ch + 1);
        asm volatile("cp.async.commit_group;");
        asm volatile("cp.async.wait_group 1;");
        __syncthreads();

        const int cb = ch << 6;
        const bool isglob = caseA && (ch == 0);
        const float* Kst = sm + OFF_K0 + (ch & 1) * KSTG;
        const float* Vst = sm + OFF_V0 + (ch & 1) * VSTG;

        float S[8][4];
#pragma unroll
        for (int nt = 0; nt < 8; ++nt)
#pragma unroll
            for (int e = 0; e < 4; ++e) S[nt][e] = 0.f;
#pragma unroll
        for (int ks = 0; ks < 16; ++ks) {
            float4 qv = *(const float4*)(qfb + ks * 128 + lane * 4);
            unsigned af[4] = {__float_as_uint(qv.x), __float_as_uint(qv.y),
                              __float_as_uint(qv.z), __float_as_uint(qv.w)};
#pragma unroll
            for (int nt = 0; nt < 8; ++nt) {
                const float* pk = Kst + (nt * 8 + g) * 132 + ks * 8 + tig;
                unsigned bf[2] = {__float_as_uint(pk[0]), __float_as_uint(pk[4])};
                mma_tf32(S[nt], af, bf);
            }
        }

        float mc0 = -2e30f, mc1 = -2e30f;
#pragma unroll
        for (int nt = 0; nt < 8; ++nt) {
            int s0 = cb + nt * 8 + 2 * tig;
#pragma unroll
            for (int e = 0; e < 2; ++e) {
                int p = kpos[s0 + e]; float ka = kadd[s0 + e];
                int r0 = qp0 + g, r1 = r0 + 8;
                bool v0, v1;
                if (isglob) { v0 = p < r0 - 256; v1 = p < r1 - 256; }
                else { v0 = (p <= r0) && (p + 255 >= r0);
                       v1 = (p <= r1) && (p + 255 >= r1); }
                S[nt][e]     = v0 ? S[nt][e] + ka     : -2e30f;
                S[nt][e + 2] = v1 ? S[nt][e + 2] + ka : -2e30f;
                mc0 = fmaxf(mc0, S[nt][e]);
                mc1 = fmaxf(mc1, S[nt][e + 2]);
            }
        }
        mc0 = fmaxf(mc0, __shfl_xor_sync(~0u, mc0, 1));
        mc0 = fmaxf(mc0, __shfl_xor_sync(~0u, mc0, 2));
        mc1 = fmaxf(mc1, __shfl_xor_sync(~0u, mc1, 1));
        mc1 = fmaxf(mc1, __shfl_xor_sync(~0u, mc1, 2));
        float mn0 = fmaxf(m0, mc0), mn1 = fmaxf(m1, mc1);
        float cr0 = __expf(m0 - mn0), cr1 = __expf(m1 - mn1);
        m0 = mn0; m1 = mn1;
        float lc0 = 0.f, lc1 = 0.f;
#pragma unroll
        for (int nt = 0; nt < 8; ++nt) {
            S[nt][0] = __expf(S[nt][0] - mn0); S[nt][1] = __expf(S[nt][1] - mn0);
            S[nt][2] = __expf(S[nt][2] - mn1); S[nt][3] = __expf(S[nt][3] - mn1);
            lc0 += S[nt][0] + S[nt][1]; lc1 += S[nt][2] + S[nt][3];
        }
        lc0 += __shfl_xor_sync(~0u, lc0, 1); lc0 += __shfl_xor_sync(~0u, lc0, 2);
        lc1 += __shfl_xor_sync(~0u, lc1, 1); lc1 += __shfl_xor_sync(~0u, lc1, 2);
        l0 = l0 * cr0 + lc0; l1 = l1 * cr1 + lc1;
#pragma unroll
        for (int dt = 0; dt < 16; ++dt) {
            oacc[dt][0] *= cr0; oacc[dt][1] *= cr0;
            oacc[dt][2] *= cr1; oacc[dt][3] *= cr1;
        }
#pragma unroll
        for (int nt = 0; nt < 8; ++nt) {
            int col = nt * 8 + 2 * tig;
            *(float2*)(Pw + g * 68 + col) =
                make_float2(cvt_tf32(S[nt][0]), cvt_tf32(S[nt][1]));
            *(float2*)(Pw + (g + 8) * 68 + col) =
                make_float2(cvt_tf32(S[nt][2]), cvt_tf32(S[nt][3]));
        }
        __syncwarp();

#pragma unroll
        for (int pk = 0; pk < 8; ++pk) {
            const float* ph = Pw + pk * 8 + tig;
            unsigned ah[4] = {__float_as_uint(ph[g * 68]),
                              __float_as_uint(ph[(g + 8) * 68]),
                              __float_as_uint(ph[g * 68 + 4]),
                              __float_as_uint(ph[(g + 8) * 68 + 4])};
#pragma unroll
            for (int dt = 0; dt < 16; ++dt) {
                const float* vh = Vst + (pk * 8 + tig) * 136 + dt * 8 + g;
                unsigned bh[2] = {__float_as_uint(vh[0]), __float_as_uint(vh[4 * 136])};
                mma_tf32(oacc[dt], ah, bh);
            }
        }
        __syncthreads();
    }

    // epilogue: write A_perm fragment-order global for GEMM2
    const float inv0 = 1.f / l0, inv1 = 1.f / l1;
    const int browA = (b * SS + qp0) >> 7;
    const int mt = (qp0 >> 4) & 7;
#pragma unroll
    for (int dt = 0; dt < 16; ++dt) {
#pragma unroll
        for (int e = 0; e < 4; ++e) {
            int k = h * 128 + dt * 8 + tig * 2 + (e & 1);
            int kt = k >> 5, ks = (k >> 3) & 3;
            int lanep = g * 4 + (k & 3);
            int r = ((e >> 1) & 1) + ((k >> 2) & 1) * 2;
            size_t off = ((size_t)(browA * 64 + kt)) * 4096
                       + (size_t)((ks * 8 + mt) * 128 + lanep * 4 + r);
            float sc = (e < 2) ? inv0 : inv1;
            attnP[off] = cvt_tf32(oacc[dt][e] * sc);
        }
    }
}

// ---------------------------------------------------------------------------
extern "C" void kernel_launch(void* const* d_in, const int* in_sizes, int n_in,
                              void* d_out, int out_size)
{
    const float* hidden = (const float*)d_in[0];
    const float* mask   = (const float*)d_in[1];
    const int*   gidx   = (const int*)d_in[2];
    const float* Wqkv   = (const float*)d_in[3];
    const float* bqkv   = (const float*)d_in[4];
    const float* Wo     = (const float*)d_in[5];
    const float* bo     = (const float*)d_in[6];
    float* out = (float*)d_out;

    float *apermH, *attnP, *wpackP, *woP, *bpack, *qraw, *qfb, *kmp, *vmp;
    cudaGetSymbolAddress((void**)&apermH, g_apermH);
    cudaGetSymbolAddress((void**)&attnP,  g_attnP);
    cudaGetSymbolAddress((void**)&wpackP, g_wpackP);
    cudaGetSymbolAddress((void**)&woP,    g_woP);
    cudaGetSymbolAddress((void**)&bpack,  g_bpack);
    cudaGetSymbolAddress((void**)&qraw,   g_qraw);
    cudaGetSymbolAddress((void**)&qfb,    g_qf);
    cudaGetSymbolAddress((void**)&kmp,    g_km);
    cudaGetSymbolAddress((void**)&vmp,    g_vm);

    cudaFuncSetAttribute(attn_mma, cudaFuncAttributeMaxDynamicSharedMemorySize,
                         ATTN2_BYTES);
    cudaFuncSetAttribute(tf32_gemm_perm, cudaFuncAttributeMaxDynamicSharedMemorySize,
                         GEMM_SMEM_BYTES);

    // 0) operand prep (all fragment-order)
    pack_w_perm<<<(unsigned)(((long)18 * 262144 + 255) / 256), 256>>>(Wqkv, wpackP, 18, 1);
    pack_w_perm<<<(unsigned)(((long)16 * 262144 + 255) / 256), 256>>>(Wo, woP, 16, 0);
    pack_b<<<(NPACK + 255) / 256, 256>>>(bqkv, bpack);
    a_perm<<<2048, 256>>>(hidden, apermH);

    // 1) fused Q + head-mean-KV GEMM
    tf32_gemm_perm<<<dim3(NPACK / 128, 4096 / 128), 256, GEMM_SMEM_BYTES>>>(
        apermH, wpackP, bpack, qraw, 4096, NPACK, 2048);

    // 2) RoPE + split; q -> fragment order, km/vm tf32-rounded
    rope_split_kernel<<<BB * SS, 128>>>(qraw, qfb, kmp, vmp);

    // 3) MMA attention (async double-buffered K/V; writes GEMM2 A_perm)
    attn_mma<<<dim3(SS / 16, BB), 512, ATTN2_BYTES>>>(
        qfb, kmp, vmp, mask, gidx, attnP);

    // 4) Output GEMM
    tf32_gemm_perm<<<dim3(2048 / 128, 4096 / 128), 256, GEMM_SMEM_BYTES>>>(
        attnP, woP, bo, out, 4096, 2048, 2048);
}